// round 16
// baseline (speedup 1.0000x reference)
#include <cuda_runtime.h>
#include <cuda_fp16.h>
#include <cstdint>

#define GS     256
#define NCLS   10
#define NPTS   262144            // 2^18
#define BATCH  16
#define CELLS  (GS * GS)         // 65536
#define TCELLS (BATCH * CELLS)   // 1,048,576
#define PTOT   (BATCH * NPTS)    // 4,194,304
#define CAP    16                // Poisson(4): P(>16) ~ 1e-6
#define IMGS   (BATCH * NCLS)    // 160
#define OUTN   (IMGS * CELLS)    // 10,485,760 floats
#define OVFMAX 8192

// ---------------------------------------------------------------------------
// Scratch — SLOT-MAJOR 32B records (one sector each):
//   uint4 #0 : v0v1, v2v3, v4v5, v6v7   (half2 bit patterns)
//   uint4 #1 : v8v9 (half2), rx (f32 bits), ry (f32 bits), pad
// g_cursor is zero at module load; reduce_kernel resets it after reading, so
// no explicit zeroing launch is needed (deterministic across graph replays).
// ---------------------------------------------------------------------------
__device__ uint32_t g_cursor[TCELLS];
__device__ __align__(128) uint4 g_pay[(size_t)CAP * TCELLS * 2];   // 512 MB
__device__ uint32_t g_ovf_cnt;       // zero at load; ovf_kernel resets
__device__ float g_ovf[OVFMAX][16];  // cellg(bits), rx, ry, v0..v9

// Zero only the tile frame (X%16==0 or Y%16==0): atomic targets of the reduce.
// Split into 3 chunks so scatter sits at ncu capture slot (launch idx 3).
#define FR_CHUNK ((OUTN + 2) / 3)
__global__ __launch_bounds__(256)
void zero_frame_kernel(float* __restrict__ out, int base) {
    const int o = base + blockIdx.x * blockDim.x + threadIdx.x;
    if (o >= OUTN || o >= base + FR_CHUNK) return;
    const int idx = o & (CELLS - 1);
    const int X = idx & 255;
    const int Y = idx >> 8;
    if ((X & 15) == 0 || (Y & 15) == 0) out[o] = 0.f;
}

__device__ __forceinline__ uint32_t h2bits(float a, float b) {
    __half2 h = __floats2half2_rn(a, b);
    return *reinterpret_cast<uint32_t*>(&h);
}
__device__ __forceinline__ float2 bits2f2(uint32_t u) {
    __half2 h = *reinterpret_cast<__half2*>(&u);
    return __half22float2(h);
}

// ---------------------------------------------------------------------------
// Pass A: scatter, FOUR points per thread (float4 loads, 4 ATOMGs in flight).
// ---------------------------------------------------------------------------
__global__ __launch_bounds__(256)
void scatter_kernel(const float* __restrict__ points,
                    const float* __restrict__ values) {
    const int gid = blockIdx.x * blockDim.x + threadIdx.x;   // 0 .. PTOT/4-1
    const int b  = gid >> 16;                 // NPTS/4 = 65536 groups per batch
    const int n0 = (gid & 65535) << 2;        // first point of this group

    const float* pb = points + (size_t)b * 2 * NPTS;
    const float4 px4 = *(const float4*)(pb + n0);
    const float4 py4 = *(const float4*)(pb + NPTS + n0);
    const float px[4] = {px4.x, px4.y, px4.z, px4.w};
    const float py[4] = {py4.x, py4.y, py4.z, py4.w};

    const float* vb = values + (size_t)b * NCLS * NPTS + n0;
    float4 vq[NCLS];
#pragma unroll
    for (int c = 0; c < NCLS; c++) vq[c] = *(const float4*)(vb + (size_t)c * NPTS);

    int   cellg[4];
    float rx[4], ry[4];
    bool  ok[4];
    uint32_t slot[4];
#pragma unroll
    for (int j = 0; j < 4; j++) {
        const float fx = (px[j] + 0.5f) * (float)GS;
        const float fy = (py[j] + 0.5f) * (float)GS;
        const float xf = floorf(fx);
        const float yf = floorf(fy);
        const int x = (int)xf;
        const int y = (int)yf;
        rx[j] = fx - xf;
        ry[j] = fy - yf;
        ok[j] = ((unsigned)x < GS) && ((unsigned)y < GS);
        cellg[j] = (b << 16) + (y << 8) + x;
        if (ok[j]) slot[j] = atomicAdd(&g_cursor[cellg[j]], 1u);  // 4 in flight
    }

#pragma unroll
    for (int j = 0; j < 4; j++) {
        if (!ok[j]) continue;
        const float v0 = (j == 0) ? vq[0].x : (j == 1) ? vq[0].y : (j == 2) ? vq[0].z : vq[0].w;
        float v[10];
#pragma unroll
        for (int c = 0; c < NCLS; c++)
            v[c] = (j == 0) ? vq[c].x : (j == 1) ? vq[c].y : (j == 2) ? vq[c].z : vq[c].w;
        (void)v0;
        if (slot[j] < CAP) {
            uint4* dst = &g_pay[((size_t)slot[j] * TCELLS + cellg[j]) * 2];
            const uint4 q0 = make_uint4(h2bits(v[0], v[1]), h2bits(v[2], v[3]),
                                        h2bits(v[4], v[5]), h2bits(v[6], v[7]));
            const uint4 q1 = make_uint4(h2bits(v[8], v[9]),
                                        __float_as_uint(rx[j]), __float_as_uint(ry[j]), 0u);
            __stcs(dst + 0, q0);
            __stcs(dst + 1, q1);
        } else {
            const uint32_t oi = atomicAdd(&g_ovf_cnt, 1u);
            if (oi < OVFMAX) {
                float* r = g_ovf[oi];
                r[0] = __uint_as_float((uint32_t)cellg[j]);
                r[1] = rx[j];  r[2] = ry[j];
#pragma unroll
                for (int c = 0; c < NCLS; c++) r[3 + c] = v[c];
            }
        }
    }
}

// ---------------------------------------------------------------------------
// Pass B: fused reduce + corner-combine, one THREAD per CELL (R14 structure).
// Also resets g_cursor for the next launch/replay.
// ---------------------------------------------------------------------------
__global__ __launch_bounds__(256, 4)
void reduce_kernel(float* __restrict__ out) {
    const int t = threadIdx.x;

    const int blk = blockIdx.x;        // 0..4095
    const int b  = blk >> 8;
    const int tt = blk & 255;
    const int ty = tt >> 4;
    const int tx = tt & 15;
    const int ly = t >> 4;
    const int lx = t & 15;

    const int cellg = (b << 16) + ((ty * 16 + ly) << 8) + (tx * 16 + lx);
    const uint32_t raw = g_cursor[cellg];
    g_cursor[cellg] = 0u;              // self-reset for next launch (replay-safe)
    const uint32_t cnt = raw < CAP ? raw : CAP;
    const uint32_t wmax = __reduce_max_sync(0xFFFFFFFFu, cnt);

    float acc[4][NCLS];
#pragma unroll
    for (int k = 0; k < 4; k++)
#pragma unroll
        for (int c = 0; c < NCLS; c++) acc[k][c] = 0.f;

    const size_t SSTR = (size_t)TCELLS * 2;    // slot stride in uint4 units
    const uint4* pa   = &g_pay[(size_t)cellg * 2];
    const uint4* pb2p = pa + SSTR;

    for (uint32_t i = 0; i < wmax; i += 2) {
        uint4 q0a, q1a, q0b, q1b;
        const bool pa_on = (i < cnt);
        const bool pb_on = (i + 1 < cnt);
        if (pa_on) {                    // batch both records' loads first (MLP)
            q0a = __ldcs(pa + 0);
            q1a = __ldcs(pa + 1);
        }
        if (pb_on) {
            q0b = __ldcs(pb2p + 0);
            q1b = __ldcs(pb2p + 1);
        }
        pa   += 2 * SSTR;
        pb2p += 2 * SSTR;
        if (pa_on) {
            const float2 f01 = bits2f2(q0a.x), f23 = bits2f2(q0a.y);
            const float2 f45 = bits2f2(q0a.z), f67 = bits2f2(q0a.w);
            const float2 f89 = bits2f2(q1a.x);
            const float rx = __uint_as_float(q1a.y);
            const float ry = __uint_as_float(q1a.z);
            const float wx0 = 1.f - rx, wy0 = 1.f - ry;
            const float w00 = wx0 * wy0, w10 = rx * wy0, w01 = wx0 * ry, w11 = rx * ry;
            const float v[10] = {f01.x, f01.y, f23.x, f23.y, f45.x,
                                 f45.y, f67.x, f67.y, f89.x, f89.y};
#pragma unroll
            for (int c = 0; c < NCLS; c++) {
                acc[0][c] += w00 * v[c];
                acc[1][c] += w10 * v[c];
                acc[2][c] += w01 * v[c];
                acc[3][c] += w11 * v[c];
            }
        }
        if (pb_on) {
            const float2 f01 = bits2f2(q0b.x), f23 = bits2f2(q0b.y);
            const float2 f45 = bits2f2(q0b.z), f67 = bits2f2(q0b.w);
            const float2 f89 = bits2f2(q1b.x);
            const float rx = __uint_as_float(q1b.y);
            const float ry = __uint_as_float(q1b.z);
            const float wx0 = 1.f - rx, wy0 = 1.f - ry;
            const float w00 = wx0 * wy0, w10 = rx * wy0, w01 = wx0 * ry, w11 = rx * ry;
            const float v[10] = {f01.x, f01.y, f23.x, f23.y, f45.x,
                                 f45.y, f67.x, f67.y, f89.x, f89.y};
#pragma unroll
            for (int c = 0; c < NCLS; c++) {
                acc[0][c] += w00 * v[c];
                acc[1][c] += w10 * v[c];
                acc[2][c] += w01 * v[c];
                acc[3][c] += w11 * v[c];
            }
        }
    }

    __shared__ float st[4][NCLS][256];
#pragma unroll
    for (int k = 0; k < 4; k++)
#pragma unroll
        for (int c = 0; c < NCLS; c++) st[k][c][t] = acc[k][c];
    __syncthreads();

    // assemble 17x17 patch: loop positions (289), inner loop classes (10).
    for (int pos = t; pos < 17 * 17; pos += 256) {
        const int oy = pos / 17;
        const int ox = pos - 17 * oy;

        const int Y = ty * 16 + oy;
        const int X = tx * 16 + ox;
        if (Y > 255 || X > 255) continue;

        const bool in00 = (oy < 16 && ox < 16);
        const bool in10 = (oy < 16 && ox >= 1);
        const bool in01 = (oy >= 1 && ox < 16);
        const bool in11 = (oy >= 1 && ox >= 1);
        const int i00 = oy * 16 + ox;
        const int i10 = i00 - 1;
        const int i01 = i00 - 16;
        const int i11 = i00 - 17;
        const bool excl = (oy != 16) && (ox != 16) &&
                          (oy != 0 || ty == 0) && (ox != 0 || tx == 0);

        float* dst = out + (((size_t)(b * NCLS)) << 16) + (Y << 8) + X;
#pragma unroll
        for (int c = 0; c < NCLS; c++) {
            float v = 0.f;
            if (in00) v += st[0][c][i00];
            if (in10) v += st[1][c][i10];
            if (in01) v += st[2][c][i01];
            if (in11) v += st[3][c][i11];
            if (excl) *dst = v;         // pure store (frame pre-zeroed)
            else      atomicAdd(dst, v);
            dst += CELLS;
        }
    }
}

// ---------------------------------------------------------------------------
// Pass C: apply rare overflow records, then reset the counter (single block).
// ---------------------------------------------------------------------------
__global__ __launch_bounds__(256)
void ovf_kernel(float* __restrict__ out) {
    const uint32_t cnt = g_ovf_cnt < OVFMAX ? g_ovf_cnt : OVFMAX;
    for (uint32_t i = threadIdx.x; i < cnt; i += 256) {
        const float* r = g_ovf[i];
        const uint32_t cellg = __float_as_uint(r[0]);
        const int b = cellg >> 16;
        const int y = (cellg >> 8) & 255;
        const int x = cellg & 255;
        const float rx = r[1], ry = r[2];
        const bool vx1 = (x + 1) < GS;
        const bool vy1 = (y + 1) < GS;
        const float wx0 = 1.f - rx, wy0 = 1.f - ry;
        const float w00 = wx0 * wy0, w10 = rx * wy0, w01 = wx0 * ry, w11 = rx * ry;
        const int i00 = (y << 8) + x;
        float* ob = out + (size_t)b * NCLS * CELLS;
#pragma unroll
        for (int c = 0; c < NCLS; c++) {
            const float v = r[3 + c];
            float* o = ob + ((size_t)c << 16);
            atomicAdd(o + i00, w00 * v);
            if (vx1)        atomicAdd(o + i00 + 1,      w10 * v);
            if (vy1)        atomicAdd(o + i00 + GS,     w01 * v);
            if (vx1 && vy1) atomicAdd(o + i00 + GS + 1, w11 * v);
        }
    }
    __syncthreads();
    if (threadIdx.x == 0) g_ovf_cnt = 0u;   // reset for next launch/replay
}

// ---------------------------------------------------------------------------
// Harness entry. zero_frame split in 3 -> scatter is launch idx 3 (profiled).
// ---------------------------------------------------------------------------
extern "C" void kernel_launch(void* const* d_in, const int* in_sizes, int n_in,
                              void* d_out, int out_size) {
    const float* points = (const float*)d_in[0];
    const float* values = (const float*)d_in[1];
    float* out = (float*)d_out;

    const int fgrid = (FR_CHUNK + 255) / 256;
    zero_frame_kernel<<<fgrid, 256>>>(out, 0);                    // idx 0
    zero_frame_kernel<<<fgrid, 256>>>(out, FR_CHUNK);             // idx 1
    zero_frame_kernel<<<fgrid, 256>>>(out, 2 * FR_CHUNK);         // idx 2
    scatter_kernel<<<PTOT / 4 / 256, 256>>>(points, values);      // idx 3 (profiled)
    reduce_kernel<<<TCELLS / 256, 256>>>(out);                    // idx 4
    ovf_kernel<<<1, 256>>>(out);                                  // idx 5
}

// round 17
// speedup vs baseline: 1.4510x; 1.4510x over previous
#include <cuda_runtime.h>
#include <cuda_fp16.h>
#include <cstdint>

#define GS     256
#define NCLS   10
#define NPTS   262144            // 2^18
#define BATCH  16
#define CELLS  (GS * GS)         // 65536
#define TCELLS (BATCH * CELLS)   // 1,048,576
#define PTOT   (BATCH * NPTS)    // 4,194,304
#define CAP    16                // Poisson(4): P(>16) ~ 1e-6
#define IMGS   (BATCH * NCLS)    // 160
#define OUTN   (IMGS * CELLS)    // 10,485,760 floats
#define OVFMAX 8192

// ---------------------------------------------------------------------------
// Scratch — SLOT-MAJOR 32B records (one sector each):
//   uint4 #0 : v0v1, v2v3, v4v5, v6v7   (half2 bit patterns)
//   uint4 #1 : v8v9 (half2), rx (f32 bits), ry (f32 bits), pad
// ---------------------------------------------------------------------------
__device__ uint32_t g_cursor[TCELLS];
__device__ __align__(128) uint4 g_pay[(size_t)CAP * TCELLS * 2];   // 512 MB
__device__ uint32_t g_ovf_cnt;
__device__ float g_ovf[OVFMAX][16];   // cellg(bits), rx, ry, v0..v9

#define CUR4   (TCELLS / 4)
#define OUTH   (OUTN / 2)
// Zero tile-frame pixels (X%16==0 or Y%16==0) for the reduce's atomics,
// plus the cursor array + overflow counter. Two launches (a: first half of
// out; b: second half + cursor) so reduce lands at ncu capture slot idx 3.
__global__ __launch_bounds__(256)
void zero_a_kernel(float* __restrict__ out) {
    const int o = blockIdx.x * blockDim.x + threadIdx.x;
    if (o >= OUTH) return;
    const int idx = o & (CELLS - 1);
    const int X = idx & 255;
    const int Y = idx >> 8;
    if ((X & 15) == 0 || (Y & 15) == 0) out[o] = 0.f;
}
__global__ __launch_bounds__(256)
void zero_b_kernel(float* __restrict__ out) {
    const int i = blockIdx.x * blockDim.x + threadIdx.x;
    const int o = OUTH + i;
    if (o < OUTN) {
        const int idx = o & (CELLS - 1);
        const int X = idx & 255;
        const int Y = idx >> 8;
        if ((X & 15) == 0 || (Y & 15) == 0) out[o] = 0.f;
    }
    if (i < CUR4) ((uint4*)g_cursor)[i] = make_uint4(0u, 0u, 0u, 0u);
    if (i == 0) g_ovf_cnt = 0u;
}

__device__ __forceinline__ uint32_t h2bits(float a, float b) {
    __half2 h = __floats2half2_rn(a, b);
    return *reinterpret_cast<uint32_t*>(&h);
}
__device__ __forceinline__ float2 bits2f2(uint32_t u) {
    __half2 h = *reinterpret_cast<__half2*>(&u);
    return __half22float2(h);
}

// ---------------------------------------------------------------------------
// Pass A: scatter into fixed-capacity slot-major buckets; overflow -> list.
// Payload stores are DEFAULT (write-back) so records stay L2-resident for the
// reduce; values reads stream with __ldcs (read-once).
// ---------------------------------------------------------------------------
__global__ __launch_bounds__(256)
void scatter_kernel(const float* __restrict__ points,
                    const float* __restrict__ values) {
    const int gid = blockIdx.x * blockDim.x + threadIdx.x;
    const int b = gid >> 18;
    const int n = gid & (NPTS - 1);

    const float* pb = points + (size_t)b * 2 * NPTS;
    const float fx = (pb[n] + 0.5f) * (float)GS;
    const float fy = (pb[NPTS + n] + 0.5f) * (float)GS;
    const float xf = floorf(fx);
    const float yf = floorf(fy);
    const int x = (int)xf;
    const int y = (int)yf;
    const float rx = fx - xf;
    const float ry = fy - yf;
    if (((unsigned)x >= GS) || ((unsigned)y >= GS)) return;

    const float* vb = values + (size_t)b * NCLS * NPTS + n;
    float v[10];
#pragma unroll
    for (int c = 0; c < NCLS; c++) v[c] = __ldcs(vb + (size_t)c * NPTS);

    const int cellg = (b << 16) + (y << 8) + x;
    const uint32_t slot = atomicAdd(&g_cursor[cellg], 1u);

    if (slot < CAP) {
        uint4* dst = &g_pay[((size_t)slot * TCELLS + cellg) * 2];
        const uint4 q0 = make_uint4(h2bits(v[0], v[1]), h2bits(v[2], v[3]),
                                    h2bits(v[4], v[5]), h2bits(v[6], v[7]));
        const uint4 q1 = make_uint4(h2bits(v[8], v[9]),
                                    __float_as_uint(rx), __float_as_uint(ry), 0u);
        dst[0] = q0;                    // default write-back: stays in L2
        dst[1] = q1;
    } else {
        const uint32_t oi = atomicAdd(&g_ovf_cnt, 1u);
        if (oi < OVFMAX) {
            float* r = g_ovf[oi];
            r[0] = __uint_as_float((uint32_t)cellg);
            r[1] = rx;  r[2] = ry;
#pragma unroll
            for (int c = 0; c < NCLS; c++) r[3 + c] = v[c];
        }
    }
}

// ---------------------------------------------------------------------------
// Pass B: fused reduce + corner-combine, one THREAD per CELL (R14 structure).
// Unroll-2 batched loads; pointer-increment addressing; positional epilogue.
// ---------------------------------------------------------------------------
__global__ __launch_bounds__(256, 4)
void reduce_kernel(float* __restrict__ out) {
    const int t = threadIdx.x;
    const int ly = t >> 4;
    const int lx = t & 15;

    const int blk = blockIdx.x;        // 0..4095
    const int b  = blk >> 8;
    const int tt = blk & 255;
    const int ty = tt >> 4;
    const int tx = tt & 15;

    const int cellg = (b << 16) + ((ty * 16 + ly) << 8) + (tx * 16 + lx);
    const uint32_t raw = g_cursor[cellg];
    const uint32_t cnt = raw < CAP ? raw : CAP;
    const uint32_t wmax = __reduce_max_sync(0xFFFFFFFFu, cnt);

    float acc[4][NCLS];
#pragma unroll
    for (int k = 0; k < 4; k++)
#pragma unroll
        for (int c = 0; c < NCLS; c++) acc[k][c] = 0.f;

    const size_t SSTR = (size_t)TCELLS * 2;    // slot stride in uint4 units
    const uint4* pa   = &g_pay[(size_t)cellg * 2];
    const uint4* pb2p = pa + SSTR;

    for (uint32_t i = 0; i < wmax; i += 2) {
        uint4 q0a, q1a, q0b, q1b;
        const bool pa_on = (i < cnt);
        const bool pb_on = (i + 1 < cnt);
        if (pa_on) {                    // batch both records' loads first (MLP)
            q0a = __ldcs(pa + 0);
            q1a = __ldcs(pa + 1);
        }
        if (pb_on) {
            q0b = __ldcs(pb2p + 0);
            q1b = __ldcs(pb2p + 1);
        }
        pa   += 2 * SSTR;
        pb2p += 2 * SSTR;
        if (pa_on) {
            const float2 f01 = bits2f2(q0a.x), f23 = bits2f2(q0a.y);
            const float2 f45 = bits2f2(q0a.z), f67 = bits2f2(q0a.w);
            const float2 f89 = bits2f2(q1a.x);
            const float rx = __uint_as_float(q1a.y);
            const float ry = __uint_as_float(q1a.z);
            const float wx0 = 1.f - rx, wy0 = 1.f - ry;
            const float w00 = wx0 * wy0, w10 = rx * wy0, w01 = wx0 * ry, w11 = rx * ry;
            const float v[10] = {f01.x, f01.y, f23.x, f23.y, f45.x,
                                 f45.y, f67.x, f67.y, f89.x, f89.y};
#pragma unroll
            for (int c = 0; c < NCLS; c++) {
                acc[0][c] += w00 * v[c];
                acc[1][c] += w10 * v[c];
                acc[2][c] += w01 * v[c];
                acc[3][c] += w11 * v[c];
            }
        }
        if (pb_on) {
            const float2 f01 = bits2f2(q0b.x), f23 = bits2f2(q0b.y);
            const float2 f45 = bits2f2(q0b.z), f67 = bits2f2(q0b.w);
            const float2 f89 = bits2f2(q1b.x);
            const float rx = __uint_as_float(q1b.y);
            const float ry = __uint_as_float(q1b.z);
            const float wx0 = 1.f - rx, wy0 = 1.f - ry;
            const float w00 = wx0 * wy0, w10 = rx * wy0, w01 = wx0 * ry, w11 = rx * ry;
            const float v[10] = {f01.x, f01.y, f23.x, f23.y, f45.x,
                                 f45.y, f67.x, f67.y, f89.x, f89.y};
#pragma unroll
            for (int c = 0; c < NCLS; c++) {
                acc[0][c] += w00 * v[c];
                acc[1][c] += w10 * v[c];
                acc[2][c] += w01 * v[c];
                acc[3][c] += w11 * v[c];
            }
        }
    }

    __shared__ float st[4][NCLS][256];
#pragma unroll
    for (int k = 0; k < 4; k++)
#pragma unroll
        for (int c = 0; c < NCLS; c++) st[k][c][t] = acc[k][c];
    __syncthreads();

    // assemble 17x17 patch: loop positions (289), inner loop classes (10).
    for (int pos = t; pos < 17 * 17; pos += 256) {
        const int oy = pos / 17;
        const int ox = pos - 17 * oy;

        const int Y = ty * 16 + oy;
        const int X = tx * 16 + ox;
        if (Y > 255 || X > 255) continue;

        const bool in00 = (oy < 16 && ox < 16);
        const bool in10 = (oy < 16 && ox >= 1);
        const bool in01 = (oy >= 1 && ox < 16);
        const bool in11 = (oy >= 1 && ox >= 1);
        const int i00 = oy * 16 + ox;
        const int i10 = i00 - 1;
        const int i01 = i00 - 16;
        const int i11 = i00 - 17;
        const bool excl = (oy != 16) && (ox != 16) &&
                          (oy != 0 || ty == 0) && (ox != 0 || tx == 0);

        float* dst = out + (((size_t)(b * NCLS)) << 16) + (Y << 8) + X;
#pragma unroll
        for (int c = 0; c < NCLS; c++) {
            float v = 0.f;
            if (in00) v += st[0][c][i00];
            if (in10) v += st[1][c][i10];
            if (in01) v += st[2][c][i01];
            if (in11) v += st[3][c][i11];
            if (excl) *dst = v;         // pure store (frame pre-zeroed)
            else      atomicAdd(dst, v);
            dst += CELLS;
        }
    }
}

// ---------------------------------------------------------------------------
// Pass C: apply rare overflow records with direct atomics (after reduce)
// ---------------------------------------------------------------------------
__global__ __launch_bounds__(256)
void ovf_kernel(float* __restrict__ out) {
    const uint32_t cnt = g_ovf_cnt < OVFMAX ? g_ovf_cnt : OVFMAX;
    for (uint32_t i = threadIdx.x; i < cnt; i += 256) {
        const float* r = g_ovf[i];
        const uint32_t cellg = __float_as_uint(r[0]);
        const int b = cellg >> 16;
        const int y = (cellg >> 8) & 255;
        const int x = cellg & 255;
        const float rx = r[1], ry = r[2];
        const bool vx1 = (x + 1) < GS;
        const bool vy1 = (y + 1) < GS;
        const float wx0 = 1.f - rx, wy0 = 1.f - ry;
        const float w00 = wx0 * wy0, w10 = rx * wy0, w01 = wx0 * ry, w11 = rx * ry;
        const int i00 = (y << 8) + x;
        float* ob = out + (size_t)b * NCLS * CELLS;
#pragma unroll
        for (int c = 0; c < NCLS; c++) {
            const float v = r[3 + c];
            float* o = ob + ((size_t)c << 16);
            atomicAdd(o + i00, w00 * v);
            if (vx1)        atomicAdd(o + i00 + 1,      w10 * v);
            if (vy1)        atomicAdd(o + i00 + GS,     w01 * v);
            if (vx1 && vy1) atomicAdd(o + i00 + GS + 1, w11 * v);
        }
    }
}

// ---------------------------------------------------------------------------
// Harness entry. Launch order puts reduce at idx 3 (ncu capture slot).
// ---------------------------------------------------------------------------
extern "C" void kernel_launch(void* const* d_in, const int* in_sizes, int n_in,
                              void* d_out, int out_size) {
    const float* points = (const float*)d_in[0];
    const float* values = (const float*)d_in[1];
    float* out = (float*)d_out;

    zero_a_kernel<<<(OUTH + 255) / 256, 256>>>(out);              // idx 0
    zero_b_kernel<<<(OUTH + 255) / 256, 256>>>(out);              // idx 1
    scatter_kernel<<<PTOT / 256, 256>>>(points, values);          // idx 2
    reduce_kernel<<<TCELLS / 256, 256>>>(out);                    // idx 3 (profiled)
    ovf_kernel<<<1, 256>>>(out);                                  // idx 4
}